// round 3
// baseline (speedup 1.0000x reference)
#include <cuda_runtime.h>
#include <math.h>

// BiTemperedLogisticLoss, T1=0.2, T2=1.2, label_smoothing=0.05, 20 fixed-point iters.
// Key identities (T2=1.2): exp_t(x) = (1-0.2x)^-5  -> one rcp + int powers.
//   p = b^-5, p^0.8 = b^-4, p^1.8 = b^-9  where b = 1 + 0.2*(lambda - a).
// Targets are one-hot -> smoothed targets take two values ON=0.95, OFF=0.05/999;
// all t-only terms fold into host-side constants.

#define C_CLASSES 1000
#define KCHUNKS   32            // 32*32 = 1024 >= 1000
#define WARPS_PER_CTA 8
#define CTA_THREADS (WARPS_PER_CTA * 32)
#define FP_ITERS  20

__device__ __forceinline__ float frcp(float x) {
    float r;
    asm("rcp.approx.ftz.f32 %0, %1;" : "=f"(r) : "f"(x));
    return r;
}

__device__ __forceinline__ float flg2(float x) {
    float r;
    asm("lg2.approx.ftz.f32 %0, %1;" : "=f"(r) : "f"(x));
    return r;
}

__device__ __forceinline__ float fex2(float x) {
    float r;
    asm("ex2.approx.ftz.f32 %0, %1;" : "=f"(r) : "f"(x));
    return r;
}

__device__ __forceinline__ float warp_sum(float v) {
#pragma unroll
    for (int o = 16; o; o >>= 1) v += __shfl_xor_sync(0xffffffffu, v, o);
    return v;
}

__device__ __forceinline__ float warp_max(float v) {
#pragma unroll
    for (int o = 16; o; o >>= 1) v = fmaxf(v, __shfl_xor_sync(0xffffffffu, v, o));
    return v;
}

__global__ void btll_init_out(float* out, int n) {
    int i = blockIdx.x * blockDim.x + threadIdx.x;
    if (i < n) out[i] = 0.0f;
}

__global__ __launch_bounds__(CTA_THREADS)
void btll_kernel(const float* __restrict__ inp, const float* __restrict__ tgt,
                 float* __restrict__ out, int N,
                 float ksum, float t_off, float t_delta, float inv_n) {
    const int warp = threadIdx.x >> 5;
    const int lane = threadIdx.x & 31;
    const int row  = blockIdx.x * WARPS_PER_CTA + warp;

    __shared__ float blk_acc;
    if (threadIdx.x == 0) blk_acc = 0.0f;
    __syncthreads();

    if (row < N) {
        const float* arow = inp + (size_t)row * C_CLASSES;

        // Load row, compute row max.
        float a[KCHUNKS];
        float mx = -3.0e38f;
#pragma unroll
        for (int k = 0; k < KCHUNKS; k++) {
            int idx = k * 32 + lane;
            float v = (idx < C_CLASSES) ? arow[idx] : -3.0e38f;
            a[k] = v;
            mx = fmaxf(mx, v);
        }
        mx = warp_max(mx);

        // e_j = 0.2*(mu - a_j) >= 0. Padding -> huge e -> contributes ~0.
        float e[KCHUNKS];
#pragma unroll
        for (int k = 0; k < KCHUNKS; k++) e[k] = 0.2f * (mx - a[k]);

        // Fixed-point iterations exactly mirroring the reference:
        // s_0 = 1; z_k = sum_j (1 + s_{k-1} e_j)^-5 ; s_k = z_k^-0.2
        // Final z computed once more with s_20.
        float s = 1.0f;
        float z = 0.0f;
        for (int it = 0; it <= FP_ITERS; ++it) {
            float acc0 = 0.0f, acc1 = 0.0f;
#pragma unroll
            for (int k = 0; k < KCHUNKS; k++) {
                float b  = fmaf(s, e[k], 1.0f);
                float r  = frcp(b);
                float r2 = r * r;
                if (k & 1) acc1 = fmaf(r2 * r2, r, acc1);
                else       acc0 = fmaf(r2 * r2, r, acc0);
            }
            z = warp_sum(acc0 + acc1);
            if (it < FP_ITERS) s = fex2(-0.2f * flg2(z));
        }
        // lambda = mu + 5*(z^0.2 - 1); in the loss pass:
        // b_j = 1 + 0.2*(lambda - a_j) = z^0.2 + e_j
        float zp = fex2(0.2f * flg2(z));

        const float* trow = tgt + (size_t)row * C_CLASSES;
        float acc4 = 0.0f, acc9 = 0.0f, acch = 0.0f;
#pragma unroll
        for (int k = 0; k < KCHUNKS; k++) {
            int idx = k * 32 + lane;
            float t  = (idx < C_CLASSES) ? trow[idx] : 0.0f;  // raw one-hot 0/1
            float b  = zp + e[k];
            float r  = frcp(b);
            float r2 = r * r;
            float r4 = r2 * r2;
            acc4 += r4;                         // sum p^0.8
            acc9  = fmaf(r4 * r4, r, acc9);     // sum p^1.8
            acch  = fmaf(t, r4, acch);          // p_hot^0.8
        }
        acc4 = warp_sum(acc4);
        acc9 = warp_sum(acc9);
        acch = warp_sum(acch);

        if (lane == 0) {
            // row_loss = sum_j [ K(t_j) - 1.25*t_j*(r4_j - 1) + r9_j/1.8 ]
            //   sum K(t_j) = ksum  (one ON + 999 OFF, host constant)
            //   sum t_j*(r4_j-1) = t_off*(acc4 - C) + t_delta*(acch - 1)
            float row_loss = ksum
                           - 1.25f * (t_off * (acc4 - (float)C_CLASSES)
                                      + t_delta * (acch - 1.0f))
                           + acc9 * (1.0f / 1.8f);
            atomicAdd(&blk_acc, row_loss * inv_n);
        }
    }
    __syncthreads();
    if (threadIdx.x == 0) atomicAdd(out, blk_acc);
}

extern "C" void kernel_launch(void* const* d_in, const int* in_sizes, int n_in,
                              void* d_out, int out_size) {
    const float* inp = (const float*)d_in[0];
    const float* tgt = (const float*)d_in[1];
    float* out = (float*)d_out;

    const int Ctot = in_sizes[0];
    const int N = Ctot / C_CLASSES;

    // Host-side constants (double precision).
    const double ls  = 0.05;
    const double off = ls / (C_CLASSES - 1);
    const double on  = (1.0 - (double)C_CLASSES / (C_CLASSES - 1) * ls) + off; // = 0.95
    // log_t(x, 0.2) = (x^0.8 - 1)/0.8 ;  K(t) = t*log_t(t+1e-8) - t^1.8/1.8
    const double logt_on  = (pow(on  + 1e-8, 0.8) - 1.0) / 0.8;
    const double logt_off = (pow(off + 1e-8, 0.8) - 1.0) / 0.8;
    const double K_on  = on  * logt_on  - pow(on,  1.8) / 1.8;
    const double K_off = off * logt_off - pow(off, 1.8) / 1.8;
    const double ksum  = K_on + (C_CLASSES - 1) * K_off;

    btll_init_out<<<1, 32>>>(out, out_size);
    int grid = (N + WARPS_PER_CTA - 1) / WARPS_PER_CTA;
    btll_kernel<<<grid, CTA_THREADS>>>(inp, tgt, out, N,
                                       (float)ksum, (float)off,
                                       (float)(on - off), (float)(1.0 / N));
}

// round 4
// speedup vs baseline: 2.2173x; 2.2173x over previous
#include <cuda_runtime.h>
#include <math.h>

// BiTemperedLogisticLoss, T1=0.2, T2=1.2, label_smoothing=0.05.
// exp_t(x, 1.2) = (1-0.2x)^-5. With u = z^0.2 and e_j = 0.2*(mu - a_j):
//   p_j = (u+e_j)^-5,  p^0.8 = b^-4,  p^1.8 = b^-9.
// Normalizer: solve phi(u) = sum_j (u+e_j)^-5 = 1 by log-Newton
// (convex decreasing in log form; monotone convergence from u0=1).
// Reference's 20 fixed-point iters are converged to ~1e-6, so converging to
// the same root matches well within 1e-3.
// One-hot targets: only the hot index matters; extracted during the load pass.

#define C_CLASSES 1000
#define KCHUNKS   32            // 32*32 = 1024 >= 1000
#define WARPS_PER_CTA 8
#define CTA_THREADS (WARPS_PER_CTA * 32)
#define NEWTON_ITERS 6

__device__ __forceinline__ float frcp(float x) {
    float r; asm("rcp.approx.ftz.f32 %0, %1;" : "=f"(r) : "f"(x)); return r;
}
__device__ __forceinline__ float flg2(float x) {
    float r; asm("lg2.approx.ftz.f32 %0, %1;" : "=f"(r) : "f"(x)); return r;
}

__device__ __forceinline__ float warp_sum(float v) {
#pragma unroll
    for (int o = 16; o; o >>= 1) v += __shfl_xor_sync(0xffffffffu, v, o);
    return v;
}
__device__ __forceinline__ float warp_max(float v) {
#pragma unroll
    for (int o = 16; o; o >>= 1) v = fmaxf(v, __shfl_xor_sync(0xffffffffu, v, o));
    return v;
}

__global__ void btll_init_out(float* out, int n) {
    int i = blockIdx.x * blockDim.x + threadIdx.x;
    if (i < n) out[i] = 0.0f;
}

__global__ __launch_bounds__(CTA_THREADS)
void btll_kernel(const float* __restrict__ inp, const float* __restrict__ tgt,
                 float* __restrict__ out, int N,
                 float ksum, float t_off, float t_delta, float inv_n) {
    const int warp = threadIdx.x >> 5;
    const int lane = threadIdx.x & 31;
    const int row  = blockIdx.x * WARPS_PER_CTA + warp;

    __shared__ float blk_acc;
    if (threadIdx.x == 0) blk_acc = 0.0f;
    __syncthreads();

    if (row < N) {
        const float* arow = inp + (size_t)row * C_CLASSES;
        const float* trow = tgt + (size_t)row * C_CLASSES;

        // Load logits + targets; row max; hot logit (one-hot targets).
        float e[KCHUNKS];
        float mx = -3.0e38f, ahot = -3.0e38f;
#pragma unroll
        for (int k = 0; k < KCHUNKS; k++) {
            int idx = k * 32 + lane;
            float v = (idx < C_CLASSES) ? arow[idx] : -3.0e38f;
            float t = (idx < C_CLASSES) ? trow[idx] : 0.0f;
            e[k] = v;
            mx = fmaxf(mx, v);
            ahot = fmaxf(ahot, (t > 0.5f) ? v : -3.0e38f);
        }
        mx = warp_max(mx);
        ahot = warp_max(ahot);
        const float e_hot = 0.2f * (mx - ahot);

        // e_j = 0.2*(mu - a_j) >= 0. Padding -> huge e -> ftz rcp^4 -> 0.
#pragma unroll
        for (int k = 0; k < KCHUNKS; k++) e[k] = 0.2f * (mx - e[k]);

        // Log-Newton on F(u) = ln(sum (u+e)^-5):
        //   u' = u + ln(S5) * S5 / (5*S6). Monotone from below, u0 = 1.
        float u = 1.0f;
#pragma unroll 1
        for (int it = 0; it < NEWTON_ITERS; ++it) {
            float s5a = 0.0f, s5b = 0.0f, s6a = 0.0f, s6b = 0.0f;
#pragma unroll
            for (int k = 0; k < KCHUNKS; k++) {
                float b  = u + e[k];
                float r  = frcp(b);
                float r2 = r * r;
                float r4 = r2 * r2;
                if (k & 1) { s5b = fmaf(r4, r,  s5b); s6b = fmaf(r4, r2, s6b); }
                else       { s5a = fmaf(r4, r,  s5a); s6a = fmaf(r4, r2, s6a); }
            }
            float S5 = warp_sum(s5a + s5b);
            float S6 = warp_sum(s6a + s6b);
            // ln(S5) = lg2(S5)*ln2 ; step = ln(S5)*S5/(5*S6)
            u = fmaf(flg2(S5) * 0.13862943611198906f, S5 * frcp(S6), u);
        }

        // Loss pass: b_j = u + e_j; p^0.8 = b^-4, p^1.8 = b^-9.
        float acc4a = 0.0f, acc4b = 0.0f, acc9a = 0.0f, acc9b = 0.0f;
#pragma unroll
        for (int k = 0; k < KCHUNKS; k++) {
            float b  = u + e[k];
            float r  = frcp(b);
            float r2 = r * r;
            float r4 = r2 * r2;
            if (k & 1) { acc4b += r4; acc9b = fmaf(r4 * r4, r, acc9b); }
            else       { acc4a += r4; acc9a = fmaf(r4 * r4, r, acc9a); }
        }
        float acc4 = warp_sum(acc4a + acc4b);
        float acc9 = warp_sum(acc9a + acc9b);

        // Hot-index p^0.8 (scalar, all lanes identical).
        float rh  = frcp(u + e_hot);
        float rh2 = rh * rh;
        float r4hot = rh2 * rh2;

        if (lane == 0) {
            // row_loss = ksum - 1.25*[t_off*(acc4 - C) + t_delta*(r4hot - 1)]
            //            + acc9/1.8
            float row_loss = ksum
                           - 1.25f * (t_off * (acc4 - (float)C_CLASSES)
                                      + t_delta * (r4hot - 1.0f))
                           + acc9 * (1.0f / 1.8f);
            atomicAdd(&blk_acc, row_loss * inv_n);
        }
    }
    __syncthreads();
    if (threadIdx.x == 0) atomicAdd(out, blk_acc);
}

extern "C" void kernel_launch(void* const* d_in, const int* in_sizes, int n_in,
                              void* d_out, int out_size) {
    const float* inp = (const float*)d_in[0];
    const float* tgt = (const float*)d_in[1];
    float* out = (float*)d_out;

    const int Ctot = in_sizes[0];
    const int N = Ctot / C_CLASSES;

    // Host-side constants (double precision).
    const double ls  = 0.05;
    const double off = ls / (C_CLASSES - 1);
    const double on  = (1.0 - (double)C_CLASSES / (C_CLASSES - 1) * ls) + off; // 0.95
    const double logt_on  = (pow(on  + 1e-8, 0.8) - 1.0) / 0.8;
    const double logt_off = (pow(off + 1e-8, 0.8) - 1.0) / 0.8;
    const double K_on  = on  * logt_on  - pow(on,  1.8) / 1.8;
    const double K_off = off * logt_off - pow(off, 1.8) / 1.8;
    const double ksum  = K_on + (C_CLASSES - 1) * K_off;

    btll_init_out<<<1, 32>>>(out, out_size);
    int grid = (N + WARPS_PER_CTA - 1) / WARPS_PER_CTA;
    btll_kernel<<<grid, CTA_THREADS>>>(inp, tgt, out, N,
                                       (float)ksum, (float)off,
                                       (float)(on - off), (float)(1.0 / N));
}

// round 5
// speedup vs baseline: 2.7282x; 1.2304x over previous
#include <cuda_runtime.h>
#include <math.h>

// BiTemperedLogisticLoss, T1=0.2, T2=1.2, label_smoothing=0.05.
// exp_t(x,1.2) = (1-0.2x)^-5. With u = z^0.2 and e_j = 0.2*(mu-a_j) >= 0:
//   p_j = (u+e_j)^-5, p^0.8 = b^-4, p^1.8 = b^-9, b = u+e.
// Solve phi(u) = sum (u+e)^-5 = 1:
//   init u1 = phi(1)^{1/5}  (provably <= root, since phi(u1) >= phi(1)/u1^5 = 1)
//   then 3 log-Newton steps: u += ln(S5)*S5/(5*S6)  (monotone, quadratic).
// Loss folds one-hot targets into two host constants + hot-index term.
// Perf: paired rcp (1 MUFU per 2 elems), f32x2 packed FMA via PTX, float4 loads.

#define C_CLASSES 1000
#define C4 250                 // float4 chunks per row
#define WARPS_PER_CTA 8
#define CTA_THREADS (WARPS_PER_CTA * 32)
#define NEWTON_ITERS 3

typedef unsigned long long u64;

__device__ __forceinline__ float frcp(float x) {
    float r; asm("rcp.approx.ftz.f32 %0, %1;" : "=f"(r) : "f"(x)); return r;
}
__device__ __forceinline__ float flg2(float x) {
    float r; asm("lg2.approx.ftz.f32 %0, %1;" : "=f"(r) : "f"(x)); return r;
}
__device__ __forceinline__ float fex2(float x) {
    float r; asm("ex2.approx.ftz.f32 %0, %1;" : "=f"(r) : "f"(x)); return r;
}

__device__ __forceinline__ u64 pk2(float lo, float hi) {
    u64 r; asm("mov.b64 %0, {%1, %2};" : "=l"(r) : "f"(lo), "f"(hi)); return r;
}
__device__ __forceinline__ void upk(u64 v, float& lo, float& hi) {
    asm("mov.b64 {%0, %1}, %2;" : "=f"(lo), "=f"(hi) : "l"(v));
}
__device__ __forceinline__ u64 add2(u64 a, u64 b) {
    u64 r; asm("add.rn.f32x2 %0, %1, %2;" : "=l"(r) : "l"(a), "l"(b)); return r;
}
__device__ __forceinline__ u64 mul2(u64 a, u64 b) {
    u64 r; asm("mul.rn.f32x2 %0, %1, %2;" : "=l"(r) : "l"(a), "l"(b)); return r;
}
__device__ __forceinline__ u64 fma2(u64 a, u64 b, u64 c) {
    u64 r; asm("fma.rn.f32x2 %0, %1, %2, %3;" : "=l"(r) : "l"(a), "l"(b), "l"(c)); return r;
}

__device__ __forceinline__ float warp_sum(float v) {
#pragma unroll
    for (int o = 16; o; o >>= 1) v += __shfl_xor_sync(0xffffffffu, v, o);
    return v;
}
__device__ __forceinline__ float warp_max(float v) {
#pragma unroll
    for (int o = 16; o; o >>= 1) v = fmaxf(v, __shfl_xor_sync(0xffffffffu, v, o));
    return v;
}

// One evaluation pass: S5 = sum (u+e)^-5, optionally S6 = sum (u+e)^-6.
// Paired reciprocal: one rcp per packed pair.
template <bool WANT6>
__device__ __forceinline__ void eval_pass(const u64* __restrict__ E, float u,
                                          float& S5, float& S6) {
    const u64 u2 = pk2(u, u);
    u64 s5 = 0ull, s6 = 0ull;   // packed {+0.f, +0.f}
#pragma unroll
    for (int p = 0; p < 16; p++) {
        u64 b = add2(u2, E[p]);
        float bl, bh; upk(b, bl, bh);
        float rp = frcp(bl * bh);
        u64 r  = mul2(pk2(rp, rp), pk2(bh, bl));  // {1/bl, 1/bh}
        u64 r2 = mul2(r, r);
        u64 r4 = mul2(r2, r2);
        s5 = fma2(r4, r, s5);
        if (WANT6) s6 = fma2(r4, r2, s6);
    }
    float x, y;
    upk(s5, x, y); S5 = warp_sum(x + y);
    if (WANT6) { upk(s6, x, y); S6 = warp_sum(x + y); }
}

__global__ void btll_init_out(float* out, int n) {
    int i = blockIdx.x * blockDim.x + threadIdx.x;
    if (i < n) out[i] = 0.0f;
}

__global__ __launch_bounds__(CTA_THREADS)
void btll_kernel(const float* __restrict__ inp, const float* __restrict__ tgt,
                 float* __restrict__ out, int N,
                 float ksum, float t_off, float t_delta, float inv_n) {
    const int warp = threadIdx.x >> 5;
    const int lane = threadIdx.x & 31;
    const int row  = blockIdx.x * WARPS_PER_CTA + warp;

    __shared__ float blk_acc;
    if (threadIdx.x == 0) blk_acc = 0.0f;
    __syncthreads();

    if (row < N) {
        const float4* a4 = (const float4*)(inp + (size_t)row * C_CLASSES);
        const float4* t4 = (const float4*)(tgt + (size_t)row * C_CLASSES);

        // Load logits (float4), row max, hot logit from one-hot targets.
        float4 va[8];
        float mx = -3.0e38f, ahot = -3.0e38f;
#pragma unroll
        for (int k = 0; k < 8; k++) {
            int c = k * 32 + lane;
            va[k] = (c < C4) ? a4[c] : make_float4(-3.0e38f, -3.0e38f, -3.0e38f, -3.0e38f);
        }
#pragma unroll
        for (int k = 0; k < 8; k++)
            mx = fmaxf(mx, fmaxf(fmaxf(va[k].x, va[k].y), fmaxf(va[k].z, va[k].w)));
#pragma unroll
        for (int k = 0; k < 8; k++) {
            int c = k * 32 + lane;
            if (c < C4) {
                float4 t = t4[c];
                ahot = fmaxf(ahot, (t.x > 0.5f) ? va[k].x : -3.0e38f);
                ahot = fmaxf(ahot, (t.y > 0.5f) ? va[k].y : -3.0e38f);
                ahot = fmaxf(ahot, (t.z > 0.5f) ? va[k].z : -3.0e38f);
                ahot = fmaxf(ahot, (t.w > 0.5f) ? va[k].w : -3.0e38f);
            }
        }
        mx   = warp_max(mx);
        ahot = warp_max(ahot);

        // e = 0.2*(mx - a); padded pairs get sentinel 1e15 (r^4 underflows to 0,
        // pair product 1e30 stays finite).
        const float mxs = 0.2f * mx;
        u64 E[16];
#pragma unroll
        for (int k = 0; k < 8; k++) {
            int c = k * 32 + lane;
            if (c < C4) {
                E[2*k]   = pk2(fmaf(-0.2f, va[k].x, mxs), fmaf(-0.2f, va[k].y, mxs));
                E[2*k+1] = pk2(fmaf(-0.2f, va[k].z, mxs), fmaf(-0.2f, va[k].w, mxs));
            } else {
                E[2*k]   = pk2(1e15f, 1e15f);
                E[2*k+1] = pk2(1e15f, 1e15f);
            }
        }

        float S5, S6;
        // Multiplicative init: u = S5(1)^{1/5}  (always <= root).
        eval_pass<false>(E, 1.0f, S5, S6);
        float u = fex2(0.2f * flg2(S5));

        // 3 log-Newton steps: u += ln(S5)*S5/(5*S6).
#pragma unroll
        for (int it = 0; it < NEWTON_ITERS; ++it) {
            eval_pass<true>(E, u, S5, S6);
            u = fmaf(flg2(S5) * 0.13862943611198906f, S5 * frcp(S6), u);
        }

        // Loss pass: acc4 = sum b^-4, acc9 = sum b^-9.
        const u64 u2 = pk2(u, u);
        u64 a4p = 0ull, a9p = 0ull;
#pragma unroll
        for (int p = 0; p < 16; p++) {
            u64 b = add2(u2, E[p]);
            float bl, bh; upk(b, bl, bh);
            float rp = frcp(bl * bh);
            u64 r  = mul2(pk2(rp, rp), pk2(bh, bl));
            u64 r2 = mul2(r, r);
            u64 r4 = mul2(r2, r2);
            a4p = add2(a4p, r4);
            u64 r8 = mul2(r4, r4);
            a9p = fma2(r8, r, a9p);
        }
        float x, y;
        upk(a4p, x, y); float acc4 = warp_sum(x + y);
        upk(a9p, x, y); float acc9 = warp_sum(x + y);

        // Hot-index b^-4 (scalar, uniform across lanes).
        float rh  = frcp(u + 0.2f * (mx - ahot));
        float rh2 = rh * rh;
        float r4hot = rh2 * rh2;

        if (lane == 0) {
            float row_loss = ksum
                           - 1.25f * (t_off * (acc4 - (float)C_CLASSES)
                                      + t_delta * (r4hot - 1.0f))
                           + acc9 * (1.0f / 1.8f);
            atomicAdd(&blk_acc, row_loss * inv_n);
        }
    }
    __syncthreads();
    if (threadIdx.x == 0) atomicAdd(out, blk_acc);
}

extern "C" void kernel_launch(void* const* d_in, const int* in_sizes, int n_in,
                              void* d_out, int out_size) {
    const float* inp = (const float*)d_in[0];
    const float* tgt = (const float*)d_in[1];
    float* out = (float*)d_out;

    const int Ctot = in_sizes[0];
    const int N = Ctot / C_CLASSES;

    // Host-side constants (double precision).
    const double ls  = 0.05;
    const double off = ls / (C_CLASSES - 1);
    const double on  = (1.0 - (double)C_CLASSES / (C_CLASSES - 1) * ls) + off; // 0.95
    const double logt_on  = (pow(on  + 1e-8, 0.8) - 1.0) / 0.8;
    const double logt_off = (pow(off + 1e-8, 0.8) - 1.0) / 0.8;
    const double K_on  = on  * logt_on  - pow(on,  1.8) / 1.8;
    const double K_off = off * logt_off - pow(off, 1.8) / 1.8;
    const double ksum  = K_on + (C_CLASSES - 1) * K_off;

    btll_init_out<<<1, 32>>>(out, out_size);
    int grid = (N + WARPS_PER_CTA - 1) / WARPS_PER_CTA;
    btll_kernel<<<grid, CTA_THREADS>>>(inp, tgt, out, N,
                                       (float)ksum, (float)off,
                                       (float)(on - off), (float)(1.0 / N));
}

// round 6
// speedup vs baseline: 2.9456x; 1.0797x over previous
#include <cuda_runtime.h>
#include <math.h>

// BiTemperedLogisticLoss, T1=0.2, T2=1.2, label_smoothing=0.05.
// exp_t(x,1.2) = (1-0.2x)^-5. With u = z^0.2 and e_j = 0.2*(mu-a_j) >= 0:
//   p_j = (u+e_j)^-5, p^0.8 = b^-4, p^1.8 = b^-9, b = u+e.
// Root solve phi(u) = sum (u+e)^-5 = 1 in 3 passes:
//   pass A (u=1): S5,S6 -> Pade init u1 = (S5/S6)*(S5^{1/5}-1) + 1
//                 (value+slope matched surrogate c*(u+eb)^-5; exact for equal e)
//   pass B: one log-Newton step  u += ln(S5)*S5/(5*S6)   (F=ln phi is convex)
//   pass C: S4,S5,S6,S9,S10; final Newton delta applied analytically:
//           acc4 = S4 - 4d*S5, acc9 = S9 - 9d*S10  (residual O(d^2)).
// One-hot targets fold to host constants + hot-index term.
// Perf: paired rcp (1 MUFU / 2 elems), f32x2 packed FMA, float4 loads.

#define C_CLASSES 1000
#define C4 250                 // float4 chunks per row
#define WARPS_PER_CTA 8
#define CTA_THREADS (WARPS_PER_CTA * 32)

typedef unsigned long long u64;

__device__ __forceinline__ float frcp(float x) {
    float r; asm("rcp.approx.ftz.f32 %0, %1;" : "=f"(r) : "f"(x)); return r;
}
__device__ __forceinline__ float flg2(float x) {
    float r; asm("lg2.approx.ftz.f32 %0, %1;" : "=f"(r) : "f"(x)); return r;
}
__device__ __forceinline__ float fex2(float x) {
    float r; asm("ex2.approx.ftz.f32 %0, %1;" : "=f"(r) : "f"(x)); return r;
}

__device__ __forceinline__ u64 pk2(float lo, float hi) {
    u64 r; asm("mov.b64 %0, {%1, %2};" : "=l"(r) : "f"(lo), "f"(hi)); return r;
}
__device__ __forceinline__ void upk(u64 v, float& lo, float& hi) {
    asm("mov.b64 {%0, %1}, %2;" : "=f"(lo), "=f"(hi) : "l"(v));
}
__device__ __forceinline__ u64 add2(u64 a, u64 b) {
    u64 r; asm("add.rn.f32x2 %0, %1, %2;" : "=l"(r) : "l"(a), "l"(b)); return r;
}
__device__ __forceinline__ u64 mul2(u64 a, u64 b) {
    u64 r; asm("mul.rn.f32x2 %0, %1, %2;" : "=l"(r) : "l"(a), "l"(b)); return r;
}
__device__ __forceinline__ u64 fma2(u64 a, u64 b, u64 c) {
    u64 r; asm("fma.rn.f32x2 %0, %1, %2, %3;" : "=l"(r) : "l"(a), "l"(b), "l"(c)); return r;
}

__device__ __forceinline__ float warp_sum(float v) {
#pragma unroll
    for (int o = 16; o; o >>= 1) v += __shfl_xor_sync(0xffffffffu, v, o);
    return v;
}
__device__ __forceinline__ float warp_max(float v) {
#pragma unroll
    for (int o = 16; o; o >>= 1) v = fmaxf(v, __shfl_xor_sync(0xffffffffu, v, o));
    return v;
}

// S5 = sum (u+e)^-5, S6 = sum (u+e)^-6 (paired rcp: one MUFU per 2 elems).
__device__ __forceinline__ void eval56(const u64* __restrict__ E, float u,
                                       float& S5, float& S6) {
    const u64 u2 = pk2(u, u);
    u64 s5 = 0ull, s6 = 0ull;
#pragma unroll
    for (int p = 0; p < 16; p++) {
        u64 b = add2(u2, E[p]);
        float bl, bh; upk(b, bl, bh);
        float rp = frcp(bl * bh);
        u64 r  = mul2(pk2(rp, rp), pk2(bh, bl));   // {1/bl, 1/bh}
        u64 r2 = mul2(r, r);
        u64 r4 = mul2(r2, r2);
        s5 = fma2(r4, r, s5);
        s6 = fma2(r4, r2, s6);
    }
    float x, y;
    upk(s5, x, y); S5 = warp_sum(x + y);
    upk(s6, x, y); S6 = warp_sum(x + y);
}

__global__ void btll_init_out(float* out, int n) {
    int i = blockIdx.x * blockDim.x + threadIdx.x;
    if (i < n) out[i] = 0.0f;
}

__global__ __launch_bounds__(CTA_THREADS, 5)
void btll_kernel(const float* __restrict__ inp, const float* __restrict__ tgt,
                 float* __restrict__ out, int N,
                 float ksum, float t_off, float t_delta, float inv_n) {
    const int warp = threadIdx.x >> 5;
    const int lane = threadIdx.x & 31;
    const int row  = blockIdx.x * WARPS_PER_CTA + warp;

    __shared__ float blk_acc;
    if (threadIdx.x == 0) blk_acc = 0.0f;
    __syncthreads();

    if (row < N) {
        const float4* a4 = (const float4*)(inp + (size_t)row * C_CLASSES);
        const float4* t4 = (const float4*)(tgt + (size_t)row * C_CLASSES);

        // Load logits (float4), row max, hot logit from one-hot targets.
        float4 va[8];
        float mx = -3.0e38f, ahot = -3.0e38f;
#pragma unroll
        for (int k = 0; k < 8; k++) {
            int c = k * 32 + lane;
            va[k] = (c < C4) ? a4[c] : make_float4(-3.0e38f, -3.0e38f, -3.0e38f, -3.0e38f);
        }
#pragma unroll
        for (int k = 0; k < 8; k++)
            mx = fmaxf(mx, fmaxf(fmaxf(va[k].x, va[k].y), fmaxf(va[k].z, va[k].w)));
#pragma unroll
        for (int k = 0; k < 8; k++) {
            int c = k * 32 + lane;
            if (c < C4) {
                float4 t = t4[c];
                ahot = fmaxf(ahot, (t.x > 0.5f) ? va[k].x : -3.0e38f);
                ahot = fmaxf(ahot, (t.y > 0.5f) ? va[k].y : -3.0e38f);
                ahot = fmaxf(ahot, (t.z > 0.5f) ? va[k].z : -3.0e38f);
                ahot = fmaxf(ahot, (t.w > 0.5f) ? va[k].w : -3.0e38f);
            }
        }
        mx   = warp_max(mx);
        ahot = warp_max(ahot);

        // e = 0.2*(mx - a); padding pairs -> sentinel 1e15 (r^4 ftz-> 0,
        // pair product 1e30 stays finite).
        const float mxs = 0.2f * mx;
        u64 E[16];
#pragma unroll
        for (int k = 0; k < 8; k++) {
            int c = k * 32 + lane;
            if (c < C4) {
                E[2*k]   = pk2(fmaf(-0.2f, va[k].x, mxs), fmaf(-0.2f, va[k].y, mxs));
                E[2*k+1] = pk2(fmaf(-0.2f, va[k].z, mxs), fmaf(-0.2f, va[k].w, mxs));
            } else {
                E[2*k]   = pk2(1e15f, 1e15f);
                E[2*k+1] = pk2(1e15f, 1e15f);
            }
        }

        float S5, S6;

        // Pass A (u=1): Pade init u = (S5/S6)*(S5^{1/5} - 1) + 1.
        eval56(E, 1.0f, S5, S6);
        float u = fmaf(S5 * frcp(S6), fex2(0.2f * flg2(S5)) - 1.0f, 1.0f);

        // Pass B: one log-Newton step.
        eval56(E, u, S5, S6);
        u = fmaf(flg2(S5) * 0.13862943611198906f, S5 * frcp(S6), u);

        // Pass C: S4,S5,S6,S9,S10; apply final Newton delta analytically.
        const u64 u2 = pk2(u, u);
        u64 s4 = 0ull, s5 = 0ull, s6 = 0ull, s9 = 0ull, s10 = 0ull;
#pragma unroll
        for (int p = 0; p < 16; p++) {
            u64 b = add2(u2, E[p]);
            float bl, bh; upk(b, bl, bh);
            float rp = frcp(bl * bh);
            u64 r  = mul2(pk2(rp, rp), pk2(bh, bl));
            u64 r2 = mul2(r, r);
            u64 r4 = mul2(r2, r2);
            u64 r8 = mul2(r4, r4);
            s4 = add2(s4, r4);
            s5 = fma2(r4, r, s5);
            s6 = fma2(r4, r2, s6);
            s9 = fma2(r8, r, s9);
            s10 = fma2(r8, r2, s10);
        }
        float x, y;
        upk(s4,  x, y); float S4  = warp_sum(x + y);
        upk(s5,  x, y);       S5  = warp_sum(x + y);
        upk(s6,  x, y);       S6  = warp_sum(x + y);
        upk(s9,  x, y); float S9  = warp_sum(x + y);
        upk(s10, x, y); float S10 = warp_sum(x + y);

        // Final Newton delta and first-order-corrected loss sums.
        float d = flg2(S5) * 0.13862943611198906f * (S5 * frcp(S6));
        float acc4 = fmaf(-4.0f * d, S5,  S4);
        float acc9 = fmaf(-9.0f * d, S10, S9);

        // Hot-index b^-4 at final u (scalar, uniform across lanes).
        float rh  = frcp((u + d) + 0.2f * (mx - ahot));
        float rh2 = rh * rh;
        float r4hot = rh2 * rh2;

        if (lane == 0) {
            float row_loss = ksum
                           - 1.25f * (t_off * (acc4 - (float)C_CLASSES)
                                      + t_delta * (r4hot - 1.0f))
                           + acc9 * (1.0f / 1.8f);
            atomicAdd(&blk_acc, row_loss * inv_n);
        }
    }
    __syncthreads();
    if (threadIdx.x == 0) atomicAdd(out, blk_acc);
}

extern "C" void kernel_launch(void* const* d_in, const int* in_sizes, int n_in,
                              void* d_out, int out_size) {
    const float* inp = (const float*)d_in[0];
    const float* tgt = (const float*)d_in[1];
    float* out = (float*)d_out;

    const int Ctot = in_sizes[0];
    const int N = Ctot / C_CLASSES;

    // Host-side constants (double precision).
    const double ls  = 0.05;
    const double off = ls / (C_CLASSES - 1);
    const double on  = (1.0 - (double)C_CLASSES / (C_CLASSES - 1) * ls) + off; // 0.95
    const double logt_on  = (pow(on  + 1e-8, 0.8) - 1.0) / 0.8;
    const double logt_off = (pow(off + 1e-8, 0.8) - 1.0) / 0.8;
    const double K_on  = on  * logt_on  - pow(on,  1.8) / 1.8;
    const double K_off = off * logt_off - pow(off, 1.8) / 1.8;
    const double ksum  = K_on + (C_CLASSES - 1) * K_off;

    btll_init_out<<<1, 32>>>(out, out_size);
    int grid = (N + WARPS_PER_CTA - 1) / WARPS_PER_CTA;
    btll_kernel<<<grid, CTA_THREADS>>>(inp, tgt, out, N,
                                       (float)ksum, (float)off,
                                       (float)(on - off), (float)(1.0 / N));
}

// round 7
// speedup vs baseline: 3.1055x; 1.0543x over previous
#include <cuda_runtime.h>
#include <math.h>

// BiTemperedLogisticLoss, T1=0.2, T2=1.2, label_smoothing=0.05.
// exp_t(x,1.2) = (1-0.2x)^-5. With u = z^0.2 and e_j = 0.2*(mu-a_j) >= 0:
//   p_j = b^-5, p^0.8 = b^-4, p^1.8 = b^-9, b = u+e_j.
// Root solve phi(u) = sum (u+e)^-5 = 1 in TWO passes:
//   pass A (u=1): S5,S6 -> Pade init u1 = (S5/S6)*(S5^{1/5}-1) + 1.
//   pass B (u1):  S4,S5,S6,S9,S10,S11; Newton step d = ln(S5)*S5/(5*S6)
//     applied analytically (binomial Taylor, F=ln phi convex so u1+d <= root):
//       acc4 = S4 - 4d*S5 + 10d^2*S6
//       acc9 = S9 - 9d*S10 + 45d^2*S11
//     hot-index term evaluated exactly at u2 = u1 + d.
// One-hot targets fold to host constants + hot-index term.
// Perf: paired rcp (1 MUFU / 2 elems), f32x2 packed FMA, float4 loads.

#define C_CLASSES 1000
#define C4 250                 // float4 chunks per row
#define WARPS_PER_CTA 8
#define CTA_THREADS (WARPS_PER_CTA * 32)

typedef unsigned long long u64;

__device__ __forceinline__ float frcp(float x) {
    float r; asm("rcp.approx.ftz.f32 %0, %1;" : "=f"(r) : "f"(x)); return r;
}
__device__ __forceinline__ float flg2(float x) {
    float r; asm("lg2.approx.ftz.f32 %0, %1;" : "=f"(r) : "f"(x)); return r;
}
__device__ __forceinline__ float fex2(float x) {
    float r; asm("ex2.approx.ftz.f32 %0, %1;" : "=f"(r) : "f"(x)); return r;
}

__device__ __forceinline__ u64 pk2(float lo, float hi) {
    u64 r; asm("mov.b64 %0, {%1, %2};" : "=l"(r) : "f"(lo), "f"(hi)); return r;
}
__device__ __forceinline__ void upk(u64 v, float& lo, float& hi) {
    asm("mov.b64 {%0, %1}, %2;" : "=f"(lo), "=f"(hi) : "l"(v));
}
__device__ __forceinline__ u64 add2(u64 a, u64 b) {
    u64 r; asm("add.rn.f32x2 %0, %1, %2;" : "=l"(r) : "l"(a), "l"(b)); return r;
}
__device__ __forceinline__ u64 mul2(u64 a, u64 b) {
    u64 r; asm("mul.rn.f32x2 %0, %1, %2;" : "=l"(r) : "l"(a), "l"(b)); return r;
}
__device__ __forceinline__ u64 fma2(u64 a, u64 b, u64 c) {
    u64 r; asm("fma.rn.f32x2 %0, %1, %2, %3;" : "=l"(r) : "l"(a), "l"(b), "l"(c)); return r;
}

__device__ __forceinline__ float warp_sum(float v) {
#pragma unroll
    for (int o = 16; o; o >>= 1) v += __shfl_xor_sync(0xffffffffu, v, o);
    return v;
}
__device__ __forceinline__ float warp_max(float v) {
#pragma unroll
    for (int o = 16; o; o >>= 1) v = fmaxf(v, __shfl_xor_sync(0xffffffffu, v, o));
    return v;
}

__global__ void btll_init_out(float* out, int n) {
    int i = blockIdx.x * blockDim.x + threadIdx.x;
    if (i < n) out[i] = 0.0f;
}

__global__ __launch_bounds__(CTA_THREADS, 5)
void btll_kernel(const float* __restrict__ inp, const float* __restrict__ tgt,
                 float* __restrict__ out, int N,
                 float ksum, float t_off, float t_delta, float inv_n) {
    const int warp = threadIdx.x >> 5;
    const int lane = threadIdx.x & 31;
    const int row  = blockIdx.x * WARPS_PER_CTA + warp;

    __shared__ float blk_acc;
    if (threadIdx.x == 0) blk_acc = 0.0f;
    __syncthreads();

    if (row < N) {
        const float4* a4 = (const float4*)(inp + (size_t)row * C_CLASSES);
        const float4* t4 = (const float4*)(tgt + (size_t)row * C_CLASSES);

        // Load logits (float4), row max, hot logit from one-hot targets.
        float4 va[8];
        float mx = -3.0e38f, ahot = -3.0e38f;
#pragma unroll
        for (int k = 0; k < 8; k++) {
            int c = k * 32 + lane;
            va[k] = (c < C4) ? a4[c] : make_float4(-3.0e38f, -3.0e38f, -3.0e38f, -3.0e38f);
        }
#pragma unroll
        for (int k = 0; k < 8; k++)
            mx = fmaxf(mx, fmaxf(fmaxf(va[k].x, va[k].y), fmaxf(va[k].z, va[k].w)));
#pragma unroll
        for (int k = 0; k < 8; k++) {
            int c = k * 32 + lane;
            if (c < C4) {
                float4 t = t4[c];
                ahot = fmaxf(ahot, (t.x > 0.5f) ? va[k].x : -3.0e38f);
                ahot = fmaxf(ahot, (t.y > 0.5f) ? va[k].y : -3.0e38f);
                ahot = fmaxf(ahot, (t.z > 0.5f) ? va[k].z : -3.0e38f);
                ahot = fmaxf(ahot, (t.w > 0.5f) ? va[k].w : -3.0e38f);
            }
        }
        mx   = warp_max(mx);
        ahot = warp_max(ahot);

        // e = 0.2*(mx - a); padding pairs -> sentinel 1e15 (r^4 ftz-> 0,
        // pair product 1e30 stays finite).
        const float mxs = 0.2f * mx;
        u64 E[16];
#pragma unroll
        for (int k = 0; k < 8; k++) {
            int c = k * 32 + lane;
            if (c < C4) {
                E[2*k]   = pk2(fmaf(-0.2f, va[k].x, mxs), fmaf(-0.2f, va[k].y, mxs));
                E[2*k+1] = pk2(fmaf(-0.2f, va[k].z, mxs), fmaf(-0.2f, va[k].w, mxs));
            } else {
                E[2*k]   = pk2(1e15f, 1e15f);
                E[2*k+1] = pk2(1e15f, 1e15f);
            }
        }

        // ---- Pass A (u = 1): S5, S6 -> Pade init.
        float u;
        {
            const u64 one2 = pk2(1.0f, 1.0f);
            u64 s5 = 0ull, s6 = 0ull;
#pragma unroll
            for (int p = 0; p < 16; p++) {
                u64 b = add2(one2, E[p]);
                float bl, bh; upk(b, bl, bh);
                float rp = frcp(bl * bh);
                u64 r  = mul2(pk2(rp, rp), pk2(bh, bl));   // {1/bl, 1/bh}
                u64 r2 = mul2(r, r);
                u64 r4 = mul2(r2, r2);
                s5 = fma2(r4, r, s5);
                s6 = fma2(r4, r2, s6);
            }
            float x, y;
            upk(s5, x, y); float S5 = warp_sum(x + y);
            upk(s6, x, y); float S6 = warp_sum(x + y);
            u = fmaf(S5 * frcp(S6), fex2(0.2f * flg2(S5)) - 1.0f, 1.0f);
        }

        // ---- Pass B (u1): all sums; analytic Newton correction.
        const u64 u2p = pk2(u, u);
        u64 s4 = 0ull, s5 = 0ull, s6 = 0ull, s9 = 0ull, s10 = 0ull, s11 = 0ull;
#pragma unroll
        for (int p = 0; p < 16; p++) {
            u64 b = add2(u2p, E[p]);
            float bl, bh; upk(b, bl, bh);
            float rp = frcp(bl * bh);
            u64 r  = mul2(pk2(rp, rp), pk2(bh, bl));
            u64 r2 = mul2(r, r);
            u64 r4 = mul2(r2, r2);
            u64 r8 = mul2(r4, r4);
            s4  = add2(s4, r4);
            s5  = fma2(r4, r,  s5);
            s6  = fma2(r4, r2, s6);
            s9  = fma2(r8, r,  s9);
            s10 = fma2(r8, r2, s10);
            s11 = fma2(r8, mul2(r2, r), s11);
        }
        float x, y;
        upk(s4,  x, y); float S4  = warp_sum(x + y);
        upk(s5,  x, y); float S5  = warp_sum(x + y);
        upk(s6,  x, y); float S6  = warp_sum(x + y);
        upk(s9,  x, y); float S9  = warp_sum(x + y);
        upk(s10, x, y); float S10 = warp_sum(x + y);
        upk(s11, x, y); float S11 = warp_sum(x + y);

        // Newton step from u1 (F = ln phi convex: u1 + d <= root, err quadratic).
        float d  = flg2(S5) * 0.13862943611198906f * (S5 * frcp(S6));
        float dd = d * d;
        float acc4 = fmaf(10.0f * dd, S6,  fmaf(-4.0f * d, S5,  S4));
        float acc9 = fmaf(45.0f * dd, S11, fmaf(-9.0f * d, S10, S9));

        // Hot-index b^-4 at u2 = u1 + d (scalar, uniform across lanes).
        float rh  = frcp((u + d) + 0.2f * (mx - ahot));
        float rh2 = rh * rh;
        float r4hot = rh2 * rh2;

        if (lane == 0) {
            float row_loss = ksum
                           - 1.25f * (t_off * (acc4 - (float)C_CLASSES)
                                      + t_delta * (r4hot - 1.0f))
                           + acc9 * (1.0f / 1.8f);
            atomicAdd(&blk_acc, row_loss * inv_n);
        }
    }
    __syncthreads();
    if (threadIdx.x == 0) atomicAdd(out, blk_acc);
}

extern "C" void kernel_launch(void* const* d_in, const int* in_sizes, int n_in,
                              void* d_out, int out_size) {
    const float* inp = (const float*)d_in[0];
    const float* tgt = (const float*)d_in[1];
    float* out = (float*)d_out;

    const int Ctot = in_sizes[0];
    const int N = Ctot / C_CLASSES;

    // Host-side constants (double precision).
    const double ls  = 0.05;
    const double off = ls / (C_CLASSES - 1);
    const double on  = (1.0 - (double)C_CLASSES / (C_CLASSES - 1) * ls) + off; // 0.95
    const double logt_on  = (pow(on  + 1e-8, 0.8) - 1.0) / 0.8;
    const double logt_off = (pow(off + 1e-8, 0.8) - 1.0) / 0.8;
    const double K_on  = on  * logt_on  - pow(on,  1.8) / 1.8;
    const double K_off = off * logt_off - pow(off, 1.8) / 1.8;
    const double ksum  = K_on + (C_CLASSES - 1) * K_off;

    btll_init_out<<<1, 32>>>(out, out_size);
    int grid = (N + WARPS_PER_CTA - 1) / WARPS_PER_CTA;
    btll_kernel<<<grid, CTA_THREADS>>>(inp, tgt, out, N,
                                       (float)ksum, (float)off,
                                       (float)(on - off), (float)(1.0 / N));
}

// round 8
// speedup vs baseline: 3.1087x; 1.0010x over previous
#include <cuda_runtime.h>
#include <math.h>

// BiTemperedLogisticLoss, T1=0.2, T2=1.2, label_smoothing=0.05.
// exp_t(x,1.2) = (1-0.2x)^-5. b_j = u + 0.2*(mu - a_j) = U - 0.2*a_j, U = u + 0.2*mu.
//   p = b^-5, p^0.8 = b^-4, p^1.8 = b^-9.
// Two passes:
//   pass A (register half only, scaled x1000/512), at u=1: S5,S6 -> Pade init
//     u1 = (S5/S6)*(S5^{1/5}-1) + 1  (init error killed quadratically below).
//   pass B (all 16 pairs: 8 reg + 8 smem): S4,S5,S6,S9,S10,S11;
//     Newton d = ln(S5)*S5/(5*S6) applied analytically:
//       acc4 = S4 - 4d*S5 + 10d^2*S6,  acc9 = S9 - 9d*S10 + 45d^2*S11.
// One-hot targets fold to host constants + hot-index term.
// Perf: raw-logit storage (fma2 fold of shift), reg/smem split for occupancy,
// paired rcp (1 MUFU / 2 elems), f32x2 packed math + packed reductions.

#define C_CLASSES 1000
#define C4 250                 // float4 chunks per row
#define WARPS_PER_CTA 8
#define CTA_THREADS (WARPS_PER_CTA * 32)

typedef unsigned long long u64;

__device__ __forceinline__ float frcp(float x) {
    float r; asm("rcp.approx.ftz.f32 %0, %1;" : "=f"(r) : "f"(x)); return r;
}
__device__ __forceinline__ float flg2(float x) {
    float r; asm("lg2.approx.ftz.f32 %0, %1;" : "=f"(r) : "f"(x)); return r;
}
__device__ __forceinline__ float fex2(float x) {
    float r; asm("ex2.approx.ftz.f32 %0, %1;" : "=f"(r) : "f"(x)); return r;
}

__device__ __forceinline__ u64 pk2(float lo, float hi) {
    u64 r; asm("mov.b64 %0, {%1, %2};" : "=l"(r) : "f"(lo), "f"(hi)); return r;
}
__device__ __forceinline__ void upk(u64 v, float& lo, float& hi) {
    asm("mov.b64 {%0, %1}, %2;" : "=f"(lo), "=f"(hi) : "l"(v));
}
__device__ __forceinline__ u64 add2(u64 a, u64 b) {
    u64 r; asm("add.rn.f32x2 %0, %1, %2;" : "=l"(r) : "l"(a), "l"(b)); return r;
}
__device__ __forceinline__ u64 mul2(u64 a, u64 b) {
    u64 r; asm("mul.rn.f32x2 %0, %1, %2;" : "=l"(r) : "l"(a), "l"(b)); return r;
}
__device__ __forceinline__ u64 fma2(u64 a, u64 b, u64 c) {
    u64 r; asm("fma.rn.f32x2 %0, %1, %2, %3;" : "=l"(r) : "l"(a), "l"(b), "l"(c)); return r;
}

// Packed butterfly reduction: sums both f32 slots across the warp.
__device__ __forceinline__ u64 warp_sum2(u64 v) {
#pragma unroll
    for (int o = 16; o; o >>= 1)
        v = add2(v, __shfl_xor_sync(0xffffffffu, v, o));
    return v;
}
__device__ __forceinline__ float warp_max(float v) {
#pragma unroll
    for (int o = 16; o; o >>= 1) v = fmaxf(v, __shfl_xor_sync(0xffffffffu, v, o));
    return v;
}

__global__ void btll_init_out(float* out, int n) {
    int i = blockIdx.x * blockDim.x + threadIdx.x;
    if (i < n) out[i] = 0.0f;
}

__global__ __launch_bounds__(CTA_THREADS, 6)
void btll_kernel(const float* __restrict__ inp, const float* __restrict__ tgt,
                 float* __restrict__ out, int N,
                 float ksum, float t_off, float t_delta, float inv_n) {
    const int tid  = threadIdx.x;
    const int warp = tid >> 5;
    const int lane = tid & 31;
    const int row  = blockIdx.x * WARPS_PER_CTA + warp;

    // Per-thread-private pair storage (no cross-thread sharing -> no barrier).
    __shared__ u64 As[8][CTA_THREADS];      // 16 KB
    __shared__ float blk_acc;
    if (tid == 0) blk_acc = 0.0f;
    __syncthreads();

    if (row < N) {
        const float4* a4 = (const float4*)(inp + (size_t)row * C_CLASSES);
        const float4* t4 = (const float4*)(tgt + (size_t)row * C_CLASSES);

        // Load: pack raw logits (pairs 0-7 -> regs, 8-15 -> smem); mx; hot logit.
        // Padding sentinel a=-1e16 -> b ~ 2e15, pair product finite, r^4 ftz->0.
        u64 Areg[8];
        float mx = -3.0e38f, ahot = -3.0e38f;
#pragma unroll
        for (int k = 0; k < 8; k++) {
            int c = k * 32 + lane;
            float4 va = (c < C4) ? a4[c]
                                 : make_float4(-1e16f, -1e16f, -1e16f, -1e16f);
            mx = fmaxf(mx, fmaxf(fmaxf(va.x, va.y), fmaxf(va.z, va.w)));
            if (c < C4) {
                float4 t = t4[c];
                ahot = fmaxf(ahot, (t.x > 0.5f) ? va.x : -3.0e38f);
                ahot = fmaxf(ahot, (t.y > 0.5f) ? va.y : -3.0e38f);
                ahot = fmaxf(ahot, (t.z > 0.5f) ? va.z : -3.0e38f);
                ahot = fmaxf(ahot, (t.w > 0.5f) ? va.w : -3.0e38f);
            }
            u64 p0 = pk2(va.x, va.y), p1 = pk2(va.z, va.w);
            if (k < 4) { Areg[2*k] = p0; Areg[2*k+1] = p1; }
            else       { As[2*(k-4)][tid] = p0; As[2*(k-4)+1][tid] = p1; }
        }
        mx   = warp_max(mx);
        ahot = warp_max(ahot);

        const float mxs = 0.2f * mx;
        const u64 negfifth = pk2(-0.2f, -0.2f);

        // ---- Pass A (registers only; 512 of 1000 elems, scaled): Pade init.
        float u;
        {
            const float U0 = 1.0f + mxs;
            const u64 U02 = pk2(U0, U0);
            u64 s5 = 0ull, s6 = 0ull;
#pragma unroll
            for (int p = 0; p < 8; p++) {
                u64 b = fma2(negfifth, Areg[p], U02);
                float bl, bh; upk(b, bl, bh);
                float rp = frcp(bl * bh);
                u64 r  = mul2(pk2(rp, rp), pk2(bh, bl));   // {1/bl, 1/bh}
                u64 r2 = mul2(r, r);
                u64 r4 = mul2(r2, r2);
                s5 = fma2(r4, r, s5);
                s6 = fma2(r4, r2, s6);
            }
            float x, y, x2, y2;
            upk(s5, x, y); upk(s6, x2, y2);
            u64 both = warp_sum2(pk2(x + y, x2 + y2));
            float S5, S6; upk(both, S5, S6);
            // ratio S5/S6 is scale-invariant; magnitude needs x(1000/512).
            u = fmaf(S5 * frcp(S6),
                     fex2(0.2f * flg2(S5 * 1.953125f)) - 1.0f, 1.0f);
        }

        // ---- Pass B (all 16 pairs) at U = u + 0.2*mx.
        const float U = u + mxs;
        const u64 U2 = pk2(U, U);
        u64 s4 = 0ull, s5 = 0ull, s6 = 0ull, s9 = 0ull, s10 = 0ull, s11 = 0ull;
#pragma unroll
        for (int p = 0; p < 16; p++) {
            u64 ap = (p < 8) ? Areg[p] : As[p - 8][tid];
            u64 b = fma2(negfifth, ap, U2);
            float bl, bh; upk(b, bl, bh);
            float rp = frcp(bl * bh);
            u64 r  = mul2(pk2(rp, rp), pk2(bh, bl));
            u64 r2 = mul2(r, r);
            u64 r4 = mul2(r2, r2);
            u64 r8 = mul2(r4, r4);
            u64 r3 = mul2(r2, r);
            s4  = add2(s4, r4);
            s5  = fma2(r4, r,  s5);
            s6  = fma2(r4, r2, s6);
            s9  = fma2(r8, r,  s9);
            s10 = fma2(r8, r2, s10);
            s11 = fma2(r8, r3, s11);
        }
        float x, y, x2, y2;
        upk(s4,  x, y); upk(s9,  x2, y2);
        u64 p49   = warp_sum2(pk2(x + y, x2 + y2));
        upk(s5,  x, y); upk(s10, x2, y2);
        u64 p510  = warp_sum2(pk2(x + y, x2 + y2));
        upk(s6,  x, y); upk(s11, x2, y2);
        u64 p611  = warp_sum2(pk2(x + y, x2 + y2));
        float S4, S9, S5, S10, S6, S11;
        upk(p49, S4, S9); upk(p510, S5, S10); upk(p611, S6, S11);

        // Newton step from u1 (F = ln phi convex), applied analytically.
        float d  = flg2(S5) * 0.13862943611198906f * (S5 * frcp(S6));
        float dd = d * d;
        float acc4 = fmaf(10.0f * dd, S6,  fmaf(-4.0f * d, S5,  S4));
        float acc9 = fmaf(45.0f * dd, S11, fmaf(-9.0f * d, S10, S9));

        // Hot-index b^-4 at u2 = u1 + d: b_hot = U + d - 0.2*ahot.
        float rh  = frcp(fmaf(-0.2f, ahot, U + d));
        float rh2 = rh * rh;
        float r4hot = rh2 * rh2;

        if (lane == 0) {
            float row_loss = ksum
                           - 1.25f * (t_off * (acc4 - (float)C_CLASSES)
                                      + t_delta * (r4hot - 1.0f))
                           + acc9 * (1.0f / 1.8f);
            atomicAdd(&blk_acc, row_loss * inv_n);
        }
    }
    __syncthreads();
    if (tid == 0) atomicAdd(out, blk_acc);
}

extern "C" void kernel_launch(void* const* d_in, const int* in_sizes, int n_in,
                              void* d_out, int out_size) {
    const float* inp = (const float*)d_in[0];
    const float* tgt = (const float*)d_in[1];
    float* out = (float*)d_out;

    const int Ctot = in_sizes[0];
    const int N = Ctot / C_CLASSES;

    // Host-side constants (double precision).
    const double ls  = 0.05;
    const double off = ls / (C_CLASSES - 1);
    const double on  = (1.0 - (double)C_CLASSES / (C_CLASSES - 1) * ls) + off; // 0.95
    const double logt_on  = (pow(on  + 1e-8, 0.8) - 1.0) / 0.8;
    const double logt_off = (pow(off + 1e-8, 0.8) - 1.0) / 0.8;
    const double K_on  = on  * logt_on  - pow(on,  1.8) / 1.8;
    const double K_off = off * logt_off - pow(off, 1.8) / 1.8;
    const double ksum  = K_on + (C_CLASSES - 1) * K_off;

    btll_init_out<<<1, 32>>>(out, out_size);
    int grid = (N + WARPS_PER_CTA - 1) / WARPS_PER_CTA;
    btll_kernel<<<grid, CTA_THREADS>>>(inp, tgt, out, N,
                                       (float)ksum, (float)off,
                                       (float)(on - off), (float)(1.0 / N));
}